// round 14
// baseline (speedup 1.0000x reference)
#include <cuda_runtime.h>
#include <cuda_bf16.h>
#include <math.h>
#include <stdint.h>

// Problem constants
#define BB   8
#define CC   256
#define NN   4096          // H*W
#define PP   32768         // B*N fused pixel index
#define NUMEL (BB*CC*NN)   // 8388608

__constant__ int c_dil[4] = {1, 2, 3, 4};
constexpr float SCALE_F = 0.17677669529663687f; // 32^-0.5
constexpr float EPS_F   = 1e-5f;

// ---------------------------------------------------------------------------
// Static device scratch (no runtime allocation)
// ---------------------------------------------------------------------------
__device__ __align__(16) __nv_bfloat16 g_xh[PP * 256];
__device__ __align__(16) __nv_bfloat16 g_xl[PP * 256];
__device__ __align__(16) __nv_bfloat16 g_yh[PP * 256];
__device__ __align__(16) __nv_bfloat16 g_yl[PP * 256];
__device__ __align__(16) __nv_bfloat16 g_wh[1024 * 256];
__device__ __align__(16) __nv_bfloat16 g_wl[1024 * 256];
__device__ __align__(16) float g_qkv[768 * PP];
__device__ __align__(16) float g_div[256 * PP];

// ---------------------------------------------------------------------------
// PTX helpers (sm_103-safe: no 'a'-only features)
// ---------------------------------------------------------------------------
__device__ __forceinline__ uint32_t cvta_smem(const void* p) {
    uint32_t a;
    asm("{ .reg .u64 t; cvta.to.shared.u64 t, %1; cvt.u32.u64 %0, t; }"
        : "=r"(a) : "l"(p));
    return a;
}

#define LDM4(r, a) \
    asm volatile("ldmatrix.sync.aligned.m8n8.x4.shared.b16 {%0,%1,%2,%3}, [%4];" \
        : "=r"((r)[0]), "=r"((r)[1]), "=r"((r)[2]), "=r"((r)[3]) : "r"(a))

#define MMA_BF16(c, a, b0_, b1_) \
    asm volatile("mma.sync.aligned.m16n8k16.row.col.f32.bf16.bf16.f32 " \
        "{%0,%1,%2,%3}, {%4,%5,%6,%7}, {%8,%9}, {%0,%1,%2,%3};" \
        : "+f"((c)[0]), "+f"((c)[1]), "+f"((c)[2]), "+f"((c)[3]) \
        : "r"((a)[0]), "r"((a)[1]), "r"((a)[2]), "r"((a)[3]), "r"(b0_), "r"(b1_))

#define CP_ASYNC16(sa, gp) \
    asm volatile("{ .reg .u64 ga; cvta.to.global.u64 ga, %1; " \
                 "cp.async.cg.shared.global [%0], [ga], 16; }" \
        :: "r"(sa), "l"(gp) : "memory")

#define CP_COMMIT() asm volatile("cp.async.commit_group;" ::: "memory")

__device__ __forceinline__ uint32_t pk2(float a, float b) {
    __nv_bfloat162 h = __floats2bfloat162_rn(a, b);
    return *reinterpret_cast<uint32_t*>(&h);
}

// ---------------------------------------------------------------------------
// Kernel W-split: bf16 hi/lo of [w_qkv ; proj_w] (1024 x 256)
// ---------------------------------------------------------------------------
__global__ __launch_bounds__(256)
void k_wsplit(const float* __restrict__ wq, const float* __restrict__ pw)
{
    const int i = blockIdx.x * 256 + threadIdx.x;
    if (i >= 1024 * 256) return;
    const float v = (i < 768 * 256) ? wq[i] : pw[i - 768 * 256];
    const __nv_bfloat16 h = __float2bfloat16(v);
    g_wh[i] = h;
    g_wl[i] = __float2bfloat16(v - __bfloat162float(h));
}

// ---------------------------------------------------------------------------
// Kernel 1: sub + LayerNorm over C, emitting bf16 hi/lo TRANSPOSED: Xt[p][k].
// ---------------------------------------------------------------------------
__global__ __launch_bounds__(256)
void k_subln(const float* __restrict__ vi, const float* __restrict__ ir,
             const float* __restrict__ ln_g, const float* __restrict__ ln_b)
{
    const int b    = blockIdx.y;
    const int pix0 = blockIdx.x * 32;
    const int tx = threadIdx.x, ty = threadIdx.y;
    const int n  = pix0 + tx;
    const size_t base = (size_t)b * CC * NN + n;

    __shared__ float s_t[32 * 257];           // [pixel][channel]
    __shared__ float s_sum[8][32], s_sq[8][32];
    __shared__ float s_mean[32], s_rstd[32];

    float vals[32];
    float s = 0.f, s2 = 0.f;
#pragma unroll
    for (int u = 0; u < 32; ++u) {
        const int c = ty + u * 8;
        const float v = vi[base + (size_t)c * NN] - ir[base + (size_t)c * NN];
        vals[u] = v; s += v; s2 += v * v;
    }
    s_sum[ty][tx] = s; s_sq[ty][tx] = s2;
    __syncthreads();
    if (ty == 0) {
        float tot = 0.f, tot2 = 0.f;
#pragma unroll
        for (int u = 0; u < 8; ++u) { tot += s_sum[u][tx]; tot2 += s_sq[u][tx]; }
        const float mean = tot * (1.0f / CC);
        const float var  = tot2 * (1.0f / CC) - mean * mean;
        s_mean[tx] = mean;
        s_rstd[tx] = rsqrtf(var + EPS_F);
    }
    __syncthreads();
    const float mean = s_mean[tx], rstd = s_rstd[tx];
#pragma unroll
    for (int u = 0; u < 32; ++u) {
        const int c = ty + u * 8;
        s_t[tx * 257 + c] = (vals[u] - mean) * rstd * ln_g[c] + ln_b[c];
    }
    __syncthreads();

    // transposed, coalesced bf16 hi/lo emission
    const int tt = ty * 32 + tx;
    const int pl = tt >> 3;
    const int c0 = (tt & 7) * 32;
    const size_t p = (size_t)b * NN + pix0 + pl;
    const float* row = &s_t[pl * 257 + c0];
    uint4* dh = reinterpret_cast<uint4*>(g_xh + p * 256 + c0);
    uint4* dl = reinterpret_cast<uint4*>(g_xl + p * 256 + c0);
#pragma unroll
    for (int q = 0; q < 4; ++q) {
        uint32_t hx[4], lx[4];
#pragma unroll
        for (int e = 0; e < 4; ++e) {
            const float f0 = row[q * 8 + e * 2];
            const float f1 = row[q * 8 + e * 2 + 1];
            const float h0 = __bfloat162float(__float2bfloat16(f0));
            const float h1 = __bfloat162float(__float2bfloat16(f1));
            hx[e] = pk2(f0, f1);
            lx[e] = pk2(f0 - h0, f1 - h1);
        }
        dh[q] = make_uint4(hx[0], hx[1], hx[2], hx[3]);
        dl[q] = make_uint4(lx[0], lx[1], lx[2], lx[3]);
    }
}

// ---------------------------------------------------------------------------
// HMMA bf16-split GEMM: C[m][p] = sum_k A[m][k] * X[k][p], K=256.
// CTA tile 128x128, BK=32, 256 threads (8 warps, 4m x 2n), warp tile 32x64.
// 3-term split: C = Ah*Bh + Al*Bh + Ah*Bl (fp32 accumulate).
// 2 CTAs/SM (launch_bounds 256,2) to cover cp.async + ldsm latency.
// ---------------------------------------------------------------------------
#define TILE_B   10240     // 128 rows * 80 B
#define STAGE_B  40960     // 4 tiles
template <int MODE>
__global__ __launch_bounds__(256, 2)
void k_gemm_mma(const float* __restrict__ bias,
                const float* __restrict__ vi,
                const float* __restrict__ ir)
{
    extern __shared__ char smem[];
    const uint32_t sb = cvta_smem(smem);
    const int t    = threadIdx.x;
    const int lane = t & 31, wid = t >> 5;
    const int p0 = blockIdx.x * 128;
    const int m0 = blockIdx.y * 128;
    const int arow0 = (MODE == 0 ? 0 : 768) + m0;

    const __nv_bfloat16* __restrict__ Bh = (MODE == 0 ? g_xh : g_yh);
    const __nv_bfloat16* __restrict__ Bl = (MODE == 0 ? g_xl : g_yl);
    float* __restrict__ Cp = (MODE == 0 ? g_qkv : g_div);

    // ---- global->smem load mapping: 4 tau groups of 64 threads ----
    const int tau = t >> 6, sub = t & 63;
    const __nv_bfloat16* __restrict__ gsrc =
        (tau == 0) ? g_wh + (size_t)arow0 * 256 :
        (tau == 1) ? g_wl + (size_t)arow0 * 256 :
        (tau == 2) ? Bh + (size_t)p0 * 256 :
                     Bl + (size_t)p0 * 256;
    const uint32_t s_tile = sb + tau * TILE_B;

    // ---- fragment lane constants ----
    const int matq = lane >> 3, l7 = lane & 7;
    const int aRow = ((matq & 1) << 3) + l7;      // row within 16
    const int aK   = (matq >> 1) << 3;            // k within 16
    const int bRow = ((matq >> 1) << 3) + l7;
    const int bK   = (matq & 1) << 3;
    const int warp_m = wid >> 1, warp_n = wid & 1;
    const int mb = warp_m * 32, nb = warp_n * 64;
    const uint32_t aOffB = (uint32_t)(mb + aRow) * 80 + aK * 2;
    const uint32_t bOffB = (uint32_t)(nb + bRow) * 80 + bK * 2;

    float acc[2][8][4] = {};

    // ---- prologue: issue chunk 0 ----
    {
        const uint32_t sdst0 = s_tile;
#pragma unroll
        for (int it = 0; it < 8; ++it) {
            const int seg = sub + it * 64;
            const int row = seg >> 2, ks = seg & 3;
            const __nv_bfloat16* gp = gsrc + (size_t)row * 256 + ks * 8;
            CP_ASYNC16(sdst0 + row * 80 + ks * 16, gp);
        }
        CP_COMMIT();
    }

    for (int ch = 0; ch < 8; ++ch) {
        if (ch < 7) {
            const int kc = (ch + 1) * 32;
            const uint32_t sdst0 = s_tile + ((ch + 1) & 1) * STAGE_B;
#pragma unroll
            for (int it = 0; it < 8; ++it) {
                const int seg = sub + it * 64;
                const int row = seg >> 2, ks = seg & 3;
                const __nv_bfloat16* gp = gsrc + (size_t)row * 256 + kc + ks * 8;
                CP_ASYNC16(sdst0 + row * 80 + ks * 16, gp);
            }
            CP_COMMIT();
            asm volatile("cp.async.wait_group 1;" ::: "memory");
        } else {
            asm volatile("cp.async.wait_group 0;" ::: "memory");
        }
        __syncthreads();

        const uint32_t st = sb + (ch & 1) * STAGE_B;
#pragma unroll
        for (int kk2 = 0; kk2 < 2; ++kk2) {
            const uint32_t kB = kk2 * 32;        // 16 bf16 = 32 bytes
            uint32_t ah[2][4], al[2][4];
#pragma unroll
            for (int i = 0; i < 2; ++i) {
                LDM4(ah[i], st + 0 * TILE_B + aOffB + i * 1280 + kB);
                LDM4(al[i], st + 1 * TILE_B + aOffB + i * 1280 + kB);
            }
#pragma unroll
            for (int j = 0; j < 4; ++j) {
                uint32_t bh[4], bl[4];
                LDM4(bh, st + 2 * TILE_B + bOffB + j * 1280 + kB);
                LDM4(bl, st + 3 * TILE_B + bOffB + j * 1280 + kB);
#pragma unroll
                for (int i = 0; i < 2; ++i)
#pragma unroll
                    for (int h = 0; h < 2; ++h) {
                        const int jn = j * 2 + h;
                        MMA_BF16(acc[i][jn], ah[i], bh[h*2], bh[h*2+1]);
                        MMA_BF16(acc[i][jn], al[i], bh[h*2], bh[h*2+1]);
                        MMA_BF16(acc[i][jn], ah[i], bl[h*2], bl[h*2+1]);
                    }
            }
        }
        __syncthreads();
    }

    // ---- epilogue ----
    const int g  = lane >> 2, tg = lane & 3;
    const int b  = p0 >> 12;          // N tile lies within one batch image
    const int n0 = p0 & 4095;
#pragma unroll
    for (int i = 0; i < 2; ++i) {
#pragma unroll
        for (int r = 0; r < 2; ++r) {
            const int m = m0 + mb + i * 16 + r * 8 + g;
            float* crow = Cp + (size_t)m * PP + p0;
            const float bb = (MODE == 1) ? bias[m] : 0.f;
            const float* vrow = vi + ((size_t)b * CC + m) * NN + n0;
            const float* irow = ir + ((size_t)b * CC + m) * NN + n0;
#pragma unroll
            for (int jn = 0; jn < 8; ++jn) {
                const int col = nb + jn * 8 + tg * 2;
                float2 v = make_float2(acc[i][jn][r*2], acc[i][jn][r*2+1]);
                if (MODE == 1) {
                    const float2 rv = *reinterpret_cast<const float2*>(vrow + col);
                    const float2 ri = *reinterpret_cast<const float2*>(irow + col);
                    v.x += bb + rv.x - ri.x;
                    v.y += bb + rv.y - ri.y;
                }
                *reinterpret_cast<float2*>(crow + col) = v;
            }
        }
    }
}

// ---------------------------------------------------------------------------
// Kernel 3: dilated local attention, lane-split over channels.
// 4 lanes (8 channels each) cooperate per (pixel, head) via shfl.bfly.
// block 256 = 8 warps; warp covers 8 pixels x 4 channel-quarters.
// grid (NN/64, 8 heads, BB).
// ---------------------------------------------------------------------------
__global__ __launch_bounds__(256)
void k_attn()
{
    const int b    = blockIdx.z;
    const int hg   = blockIdx.y;               // global head 0..7
    const int warp = threadIdx.x >> 5, lane = threadIdx.x & 31;
    const int n    = blockIdx.x * 64 + warp * 8 + (lane & 7);
    const int qtr  = lane >> 3;                // channel quarter 0..3
    const int g    = hg >> 1;                  // dilation group
    const int dil  = c_dil[g];
    const int qc   = g * 64 + (hg & 1) * 32;   // channel base within 256
    const int c0   = qtr * 8;

    const float* __restrict__ qp = g_qkv + (size_t)(qc + c0) * PP + (size_t)b * NN;
    const float* __restrict__ kp = g_qkv + (size_t)(256 + qc + c0) * PP + (size_t)b * NN;
    const float* __restrict__ vp = g_qkv + (size_t)(512 + qc + c0) * PP + (size_t)b * NN;

    const int yy = n >> 6, xx = n & 63;

    float q[8];
#pragma unroll
    for (int c = 0; c < 8; ++c) q[c] = qp[(size_t)c * PP + n];

    float logit[9];
    float mx = -1e30f;
#pragma unroll
    for (int t = 0; t < 9; ++t) {
        const int py = yy + (t / 3 - 1) * dil;
        const int px = xx + (t % 3 - 1) * dil;
        float s = 0.f;
        if ((unsigned)py < 64u && (unsigned)px < 64u) {
            const float* kcol = kp + py * 64 + px;
#pragma unroll
            for (int c = 0; c < 8; ++c) s += q[c] * kcol[(size_t)c * PP];
        }
        // reduce across the 4 channel-quarters (lanes l, l^8, l^16, l^24)
        s += __shfl_xor_sync(0xFFFFFFFFu, s, 8);
        s += __shfl_xor_sync(0xFFFFFFFFu, s, 16);
        s *= SCALE_F;           // zero-padded taps give exactly 0 (matches Unfold)
        logit[t] = s;
        mx = fmaxf(mx, s);
    }
    float den = 0.f;
#pragma unroll
    for (int t = 0; t < 9; ++t) { logit[t] = expf(logit[t] - mx); den += logit[t]; }
    const float inv = 1.0f / den;

    float acc[8] = {};
#pragma unroll
    for (int t = 0; t < 9; ++t) {
        const int py = yy + (t / 3 - 1) * dil;
        const int px = xx + (t % 3 - 1) * dil;
        if ((unsigned)py < 64u && (unsigned)px < 64u) {
            const float p = logit[t] * inv;
            const float* vcol = vp + py * 64 + px;
#pragma unroll
            for (int c = 0; c < 8; ++c) acc[c] += p * vcol[(size_t)c * PP];
        }
    }

    // bf16 hi/lo, transposed out: Yt[p][qc+c0 .. +8] = one uint4 each
    const size_t p = (size_t)b * NN + n;
    uint32_t hx[4], lx[4];
#pragma unroll
    for (int e = 0; e < 4; ++e) {
        const float f0 = acc[e * 2];
        const float f1 = acc[e * 2 + 1];
        const float h0 = __bfloat162float(__float2bfloat16(f0));
        const float h1 = __bfloat162float(__float2bfloat16(f1));
        hx[e] = pk2(f0, f1);
        lx[e] = pk2(f0 - h0, f1 - h1);
    }
    *reinterpret_cast<uint4*>(g_yh + p * 256 + qc + c0) = make_uint4(hx[0], hx[1], hx[2], hx[3]);
    *reinterpret_cast<uint4*>(g_yl + p * 256 + qc + c0) = make_uint4(lx[0], lx[1], lx[2], lx[3]);
}

// ---------------------------------------------------------------------------
// Kernel 5: per-(b,c) 64x64 @ 64x64 matmul: o = vi[b,c] @ div[b,c].
// g_div layout is [c][b*4096 + n].
// ---------------------------------------------------------------------------
__global__ __launch_bounds__(256)
void k_final(const float* __restrict__ vi, float* __restrict__ out, int dup)
{
    const int bc = blockIdx.x;
    const int b = bc >> 8, c = bc & 255;
    const float* __restrict__ Ap = vi    + (size_t)bc * 4096;
    const float* __restrict__ Bp = g_div + (size_t)c * PP + (size_t)b * NN;

    __shared__ __align__(16) float Asm[64][68];  // transposed
    __shared__ __align__(16) float Bsm[64][64];

    const int t  = threadIdx.x;
    const int tx = t & 15, ty = t >> 4;

#pragma unroll
    for (int it = 0; it < 4; ++it) {
        const int e  = t + 256 * it;
        const int r  = e >> 4;
        const int c4 = (e & 15) * 4;
        const float4 a4 = *reinterpret_cast<const float4*>(Ap + r * 64 + c4);
        Asm[c4 + 0][r] = a4.x; Asm[c4 + 1][r] = a4.y;
        Asm[c4 + 2][r] = a4.z; Asm[c4 + 3][r] = a4.w;
        *reinterpret_cast<float4*>(&Bsm[r][c4]) =
            *reinterpret_cast<const float4*>(Bp + r * 64 + c4);
    }
    __syncthreads();

    float acc[4][4] = {};
#pragma unroll
    for (int k = 0; k < 64; ++k) {
        float a_[4], b_[4];
#pragma unroll
        for (int i = 0; i < 4; ++i) a_[i] = Asm[k][ty * 4 + i];
#pragma unroll
        for (int j = 0; j < 4; ++j) b_[j] = Bsm[k][tx * 4 + j];
#pragma unroll
        for (int i = 0; i < 4; ++i)
#pragma unroll
            for (int j = 0; j < 4; ++j)
                acc[i][j] += a_[i] * b_[j];
    }

#pragma unroll
    for (int i = 0; i < 4; ++i) {
        const size_t idx = (size_t)bc * 4096 + (size_t)(ty * 4 + i) * 64 + tx * 4;
        const float4 v = make_float4(acc[i][0], acc[i][1], acc[i][2], acc[i][3]);
        *reinterpret_cast<float4*>(out + idx) = v;
        if (dup) *reinterpret_cast<float4*>(out + (size_t)NUMEL + idx) = v;
    }
}

// ---------------------------------------------------------------------------
extern "C" void kernel_launch(void* const* d_in, const int* in_sizes, int n_in,
                              void* d_out, int out_size)
{
    const float* vi     = (const float*)d_in[0];
    const float* ir     = (const float*)d_in[1];
    const float* w_qkv  = (const float*)d_in[2];
    const float* proj_w = (const float*)d_in[3];
    const float* proj_b = (const float*)d_in[4];
    const float* ln_g   = (const float*)d_in[5];
    const float* ln_b   = (const float*)d_in[6];
    float* out = (float*)d_out;

    const int dup = (out_size >= 2 * NUMEL) ? 1 : 0;
    const int SMEM_GEMM = 2 * STAGE_B;   // 81920 B

    static bool attr_done = false;
    if (!attr_done) {
        cudaFuncSetAttribute(k_gemm_mma<0>, cudaFuncAttributeMaxDynamicSharedMemorySize, SMEM_GEMM);
        cudaFuncSetAttribute(k_gemm_mma<1>, cudaFuncAttributeMaxDynamicSharedMemorySize, SMEM_GEMM);
        attr_done = true;
    }

    // 0. weight bf16 split
    k_wsplit<<<1024, 256>>>(w_qkv, proj_w);
    // 1. sub + LN -> Xt hi/lo (transposed bf16 split)
    k_subln<<<dim3(NN / 32, BB), dim3(32, 8)>>>(vi, ir, ln_g, ln_b);
    // 2. QKV GEMM (HMMA): g_qkv[768][32768]
    k_gemm_mma<0><<<dim3(PP / 128, 6), 256, SMEM_GEMM>>>(nullptr, nullptr, nullptr);
    // 3. dilated local attention -> Yt hi/lo
    k_attn<<<dim3(NN / 64, 8, BB), 256>>>();
    // 4. proj GEMM (HMMA) + bias + residual -> g_div[256][32768]
    k_gemm_mma<1><<<dim3(PP / 128, 2), 256, SMEM_GEMM>>>(proj_b, vi, ir);
    // 5. batched 64x64 matmul: out = vi @ div, duplicated
    k_final<<<BB * CC, 256>>>(vi, out, dup);
}

// round 15
// speedup vs baseline: 1.1083x; 1.1083x over previous
#include <cuda_runtime.h>
#include <cuda_bf16.h>
#include <math.h>
#include <stdint.h>

// Problem constants
#define BB   8
#define CC   256
#define NN   4096          // H*W
#define PP   32768         // B*N fused pixel index
#define NUMEL (BB*CC*NN)   // 8388608

__constant__ int c_dil[4] = {1, 2, 3, 4};
constexpr float SCALE_F = 0.17677669529663687f; // 32^-0.5
constexpr float EPS_F   = 1e-5f;

// ---------------------------------------------------------------------------
// Static device scratch (no runtime allocation)
// ---------------------------------------------------------------------------
__device__ __align__(16) __nv_bfloat16 g_xh[PP * 256];
__device__ __align__(16) __nv_bfloat16 g_xl[PP * 256];
__device__ __align__(16) __nv_bfloat16 g_yh[PP * 256];
__device__ __align__(16) __nv_bfloat16 g_yl[PP * 256];
__device__ __align__(16) __nv_bfloat16 g_wh[1024 * 256];
__device__ __align__(16) __nv_bfloat16 g_wl[1024 * 256];
__device__ __align__(16) float g_qkv[768 * PP];
__device__ __align__(16) float g_div[256 * PP];

// ---------------------------------------------------------------------------
// PTX helpers (sm_103-safe: no 'a'-only features)
// ---------------------------------------------------------------------------
__device__ __forceinline__ uint32_t cvta_smem(const void* p) {
    uint32_t a;
    asm("{ .reg .u64 t; cvta.to.shared.u64 t, %1; cvt.u32.u64 %0, t; }"
        : "=r"(a) : "l"(p));
    return a;
}

#define LDM4(r, a) \
    asm volatile("ldmatrix.sync.aligned.m8n8.x4.shared.b16 {%0,%1,%2,%3}, [%4];" \
        : "=r"((r)[0]), "=r"((r)[1]), "=r"((r)[2]), "=r"((r)[3]) : "r"(a))

#define MMA_BF16(c, a, b0_, b1_) \
    asm volatile("mma.sync.aligned.m16n8k16.row.col.f32.bf16.bf16.f32 " \
        "{%0,%1,%2,%3}, {%4,%5,%6,%7}, {%8,%9}, {%0,%1,%2,%3};" \
        : "+f"((c)[0]), "+f"((c)[1]), "+f"((c)[2]), "+f"((c)[3]) \
        : "r"((a)[0]), "r"((a)[1]), "r"((a)[2]), "r"((a)[3]), "r"(b0_), "r"(b1_))

#define CP_ASYNC16(sa, gp) \
    asm volatile("{ .reg .u64 ga; cvta.to.global.u64 ga, %1; " \
                 "cp.async.cg.shared.global [%0], [ga], 16; }" \
        :: "r"(sa), "l"(gp) : "memory")

#define CP_COMMIT() asm volatile("cp.async.commit_group;" ::: "memory")

__device__ __forceinline__ uint32_t pk2(float a, float b) {
    __nv_bfloat162 h = __floats2bfloat162_rn(a, b);
    return *reinterpret_cast<uint32_t*>(&h);
}

// ---------------------------------------------------------------------------
// Kernel W-split: bf16 hi/lo of [w_qkv ; proj_w] (1024 x 256)
// ---------------------------------------------------------------------------
__global__ __launch_bounds__(256)
void k_wsplit(const float* __restrict__ wq, const float* __restrict__ pw)
{
    const int i = blockIdx.x * 256 + threadIdx.x;
    if (i >= 1024 * 256) return;
    const float v = (i < 768 * 256) ? wq[i] : pw[i - 768 * 256];
    const __nv_bfloat16 h = __float2bfloat16(v);
    g_wh[i] = h;
    g_wl[i] = __float2bfloat16(v - __bfloat162float(h));
}

// ---------------------------------------------------------------------------
// Kernel 1: sub + LayerNorm over C, emitting bf16 hi/lo TRANSPOSED: Xt[p][k].
// ---------------------------------------------------------------------------
__global__ __launch_bounds__(256)
void k_subln(const float* __restrict__ vi, const float* __restrict__ ir,
             const float* __restrict__ ln_g, const float* __restrict__ ln_b)
{
    const int b    = blockIdx.y;
    const int pix0 = blockIdx.x * 32;
    const int tx = threadIdx.x, ty = threadIdx.y;
    const int n  = pix0 + tx;
    const size_t base = (size_t)b * CC * NN + n;

    __shared__ float s_t[32 * 257];           // [pixel][channel]
    __shared__ float s_sum[8][32], s_sq[8][32];
    __shared__ float s_mean[32], s_rstd[32];

    float vals[32];
    float s = 0.f, s2 = 0.f;
#pragma unroll
    for (int u = 0; u < 32; ++u) {
        const int c = ty + u * 8;
        const float v = vi[base + (size_t)c * NN] - ir[base + (size_t)c * NN];
        vals[u] = v; s += v; s2 += v * v;
    }
    s_sum[ty][tx] = s; s_sq[ty][tx] = s2;
    __syncthreads();
    if (ty == 0) {
        float tot = 0.f, tot2 = 0.f;
#pragma unroll
        for (int u = 0; u < 8; ++u) { tot += s_sum[u][tx]; tot2 += s_sq[u][tx]; }
        const float mean = tot * (1.0f / CC);
        const float var  = tot2 * (1.0f / CC) - mean * mean;
        s_mean[tx] = mean;
        s_rstd[tx] = rsqrtf(var + EPS_F);
    }
    __syncthreads();
    const float mean = s_mean[tx], rstd = s_rstd[tx];
#pragma unroll
    for (int u = 0; u < 32; ++u) {
        const int c = ty + u * 8;
        s_t[tx * 257 + c] = (vals[u] - mean) * rstd * ln_g[c] + ln_b[c];
    }
    __syncthreads();

    // transposed, coalesced bf16 hi/lo emission
    const int tt = ty * 32 + tx;
    const int pl = tt >> 3;
    const int c0 = (tt & 7) * 32;
    const size_t p = (size_t)b * NN + pix0 + pl;
    const float* row = &s_t[pl * 257 + c0];
    uint4* dh = reinterpret_cast<uint4*>(g_xh + p * 256 + c0);
    uint4* dl = reinterpret_cast<uint4*>(g_xl + p * 256 + c0);
#pragma unroll
    for (int q = 0; q < 4; ++q) {
        uint32_t hx[4], lx[4];
#pragma unroll
        for (int e = 0; e < 4; ++e) {
            const float f0 = row[q * 8 + e * 2];
            const float f1 = row[q * 8 + e * 2 + 1];
            const float h0 = __bfloat162float(__float2bfloat16(f0));
            const float h1 = __bfloat162float(__float2bfloat16(f1));
            hx[e] = pk2(f0, f1);
            lx[e] = pk2(f0 - h0, f1 - h1);
        }
        dh[q] = make_uint4(hx[0], hx[1], hx[2], hx[3]);
        dl[q] = make_uint4(lx[0], lx[1], lx[2], lx[3]);
    }
}

// ---------------------------------------------------------------------------
// HMMA bf16-split GEMM: C[m][p] = sum_k A[m][k] * X[k][p], K=256.
// CTA tile 128x128, BK=32, 256 threads (8 warps, 4m x 2n), warp tile 32x64.
// 3-term split: C = Ah*Bh + Al*Bh + Ah*Bl (fp32 accumulate).
// 2 CTAs/SM (launch_bounds 256,2) to cover cp.async + ldsm latency.
// ---------------------------------------------------------------------------
#define TILE_B   10240     // 128 rows * 80 B
#define STAGE_B  40960     // 4 tiles
template <int MODE>
__global__ __launch_bounds__(256, 2)
void k_gemm_mma(const float* __restrict__ bias,
                const float* __restrict__ vi,
                const float* __restrict__ ir)
{
    extern __shared__ char smem[];
    const uint32_t sb = cvta_smem(smem);
    const int t    = threadIdx.x;
    const int lane = t & 31, wid = t >> 5;
    const int p0 = blockIdx.x * 128;
    const int m0 = blockIdx.y * 128;
    const int arow0 = (MODE == 0 ? 0 : 768) + m0;

    const __nv_bfloat16* __restrict__ Bh = (MODE == 0 ? g_xh : g_yh);
    const __nv_bfloat16* __restrict__ Bl = (MODE == 0 ? g_xl : g_yl);
    float* __restrict__ Cp = (MODE == 0 ? g_qkv : g_div);

    // ---- global->smem load mapping: 4 tau groups of 64 threads ----
    const int tau = t >> 6, sub = t & 63;
    const __nv_bfloat16* __restrict__ gsrc =
        (tau == 0) ? g_wh + (size_t)arow0 * 256 :
        (tau == 1) ? g_wl + (size_t)arow0 * 256 :
        (tau == 2) ? Bh + (size_t)p0 * 256 :
                     Bl + (size_t)p0 * 256;
    const uint32_t s_tile = sb + tau * TILE_B;

    // ---- fragment lane constants ----
    const int matq = lane >> 3, l7 = lane & 7;
    const int aRow = ((matq & 1) << 3) + l7;      // row within 16
    const int aK   = (matq >> 1) << 3;            // k within 16
    const int bRow = ((matq >> 1) << 3) + l7;
    const int bK   = (matq & 1) << 3;
    const int warp_m = wid >> 1, warp_n = wid & 1;
    const int mb = warp_m * 32, nb = warp_n * 64;
    const uint32_t aOffB = (uint32_t)(mb + aRow) * 80 + aK * 2;
    const uint32_t bOffB = (uint32_t)(nb + bRow) * 80 + bK * 2;

    float acc[2][8][4] = {};

    // ---- prologue: issue chunk 0 ----
    {
        const uint32_t sdst0 = s_tile;
#pragma unroll
        for (int it = 0; it < 8; ++it) {
            const int seg = sub + it * 64;
            const int row = seg >> 2, ks = seg & 3;
            const __nv_bfloat16* gp = gsrc + (size_t)row * 256 + ks * 8;
            CP_ASYNC16(sdst0 + row * 80 + ks * 16, gp);
        }
        CP_COMMIT();
    }

    for (int ch = 0; ch < 8; ++ch) {
        if (ch < 7) {
            const int kc = (ch + 1) * 32;
            const uint32_t sdst0 = s_tile + ((ch + 1) & 1) * STAGE_B;
#pragma unroll
            for (int it = 0; it < 8; ++it) {
                const int seg = sub + it * 64;
                const int row = seg >> 2, ks = seg & 3;
                const __nv_bfloat16* gp = gsrc + (size_t)row * 256 + kc + ks * 8;
                CP_ASYNC16(sdst0 + row * 80 + ks * 16, gp);
            }
            CP_COMMIT();
            asm volatile("cp.async.wait_group 1;" ::: "memory");
        } else {
            asm volatile("cp.async.wait_group 0;" ::: "memory");
        }
        __syncthreads();

        const uint32_t st = sb + (ch & 1) * STAGE_B;
#pragma unroll
        for (int kk2 = 0; kk2 < 2; ++kk2) {
            const uint32_t kB = kk2 * 32;        // 16 bf16 = 32 bytes
            uint32_t ah[2][4], al[2][4];
#pragma unroll
            for (int i = 0; i < 2; ++i) {
                LDM4(ah[i], st + 0 * TILE_B + aOffB + i * 1280 + kB);
                LDM4(al[i], st + 1 * TILE_B + aOffB + i * 1280 + kB);
            }
#pragma unroll
            for (int j = 0; j < 4; ++j) {
                uint32_t bh[4], bl[4];
                LDM4(bh, st + 2 * TILE_B + bOffB + j * 1280 + kB);
                LDM4(bl, st + 3 * TILE_B + bOffB + j * 1280 + kB);
#pragma unroll
                for (int i = 0; i < 2; ++i)
#pragma unroll
                    for (int h = 0; h < 2; ++h) {
                        const int jn = j * 2 + h;
                        MMA_BF16(acc[i][jn], ah[i], bh[h*2], bh[h*2+1]);
                        MMA_BF16(acc[i][jn], al[i], bh[h*2], bh[h*2+1]);
                        MMA_BF16(acc[i][jn], ah[i], bl[h*2], bl[h*2+1]);
                    }
            }
        }
        __syncthreads();
    }

    // ---- epilogue ----
    const int g  = lane >> 2, tg = lane & 3;
    const int b  = p0 >> 12;          // N tile lies within one batch image
    const int n0 = p0 & 4095;
#pragma unroll
    for (int i = 0; i < 2; ++i) {
#pragma unroll
        for (int r = 0; r < 2; ++r) {
            const int m = m0 + mb + i * 16 + r * 8 + g;
            float* crow = Cp + (size_t)m * PP + p0;
            const float bb = (MODE == 1) ? bias[m] : 0.f;
            const float* vrow = vi + ((size_t)b * CC + m) * NN + n0;
            const float* irow = ir + ((size_t)b * CC + m) * NN + n0;
#pragma unroll
            for (int jn = 0; jn < 8; ++jn) {
                const int col = nb + jn * 8 + tg * 2;
                float2 v = make_float2(acc[i][jn][r*2], acc[i][jn][r*2+1]);
                if (MODE == 1) {
                    const float2 rv = *reinterpret_cast<const float2*>(vrow + col);
                    const float2 ri = *reinterpret_cast<const float2*>(irow + col);
                    v.x += bb + rv.x - ri.x;
                    v.y += bb + rv.y - ri.y;
                }
                *reinterpret_cast<float2*>(crow + col) = v;
            }
        }
    }
}

// ---------------------------------------------------------------------------
// Kernel 3: dilated local attention. One thread per (b, head, pixel) with
// channels processed in two halves of 16 to keep register pressure < 64
// while preserving fully-coalesced 128B warp loads.
// grid (NN/256, 8 heads, BB), block 256.
// ---------------------------------------------------------------------------
__global__ __launch_bounds__(256)
void k_attn()
{
    const int b  = blockIdx.z;
    const int hg = blockIdx.y;               // global head 0..7
    const int n  = blockIdx.x * 256 + threadIdx.x;
    const int g  = hg >> 1;                  // dilation group
    const int dil = c_dil[g];
    const int qc = g * 64 + (hg & 1) * 32;   // channel base within 256

    const float* __restrict__ qp = g_qkv + (size_t)qc * PP + (size_t)b * NN;
    const float* __restrict__ kp = g_qkv + (size_t)(256 + qc) * PP + (size_t)b * NN;
    const float* __restrict__ vp = g_qkv + (size_t)(512 + qc) * PP + (size_t)b * NN;

    const int yy = n >> 6, xx = n & 63;

    // tap geometry (precompute validity + offset once)
    int   toff[9];
    bool  tok[9];
#pragma unroll
    for (int t = 0; t < 9; ++t) {
        const int py = yy + (t / 3 - 1) * dil;
        const int px = xx + (t % 3 - 1) * dil;
        tok[t]  = ((unsigned)py < 64u) && ((unsigned)px < 64u);
        toff[t] = py * 64 + px;
    }

    // ---- Pass A: logits over two channel halves ----
    float logit[9] = {0.f, 0.f, 0.f, 0.f, 0.f, 0.f, 0.f, 0.f, 0.f};
#pragma unroll
    for (int half = 0; half < 2; ++half) {
        const float* qph = qp + (size_t)(half * 16) * PP;
        const float* kph = kp + (size_t)(half * 16) * PP;
        float q[16];
#pragma unroll
        for (int c = 0; c < 16; ++c) q[c] = qph[(size_t)c * PP + n];
#pragma unroll
        for (int t = 0; t < 9; ++t) {
            if (tok[t]) {
                const float* kcol = kph + toff[t];
                float s = 0.f;
#pragma unroll
                for (int c = 0; c < 16; ++c) s += q[c] * kcol[(size_t)c * PP];
                logit[t] += s;
            }
        }
    }

    float mx = -1e30f;
#pragma unroll
    for (int t = 0; t < 9; ++t) {
        logit[t] *= SCALE_F;       // zero-padded taps give exactly 0 (matches Unfold)
        mx = fmaxf(mx, logit[t]);
    }
    float den = 0.f;
#pragma unroll
    for (int t = 0; t < 9; ++t) { logit[t] = expf(logit[t] - mx); den += logit[t]; }
    const float inv = 1.0f / den;
#pragma unroll
    for (int t = 0; t < 9; ++t) logit[t] *= inv;

    // ---- Pass B: AV per half, write out immediately ----
    const size_t p = (size_t)b * NN + n;
#pragma unroll
    for (int half = 0; half < 2; ++half) {
        const float* vph = vp + (size_t)(half * 16) * PP;
        float acc[16] = {};
#pragma unroll
        for (int t = 0; t < 9; ++t) {
            if (tok[t]) {
                const float pw = logit[t];
                const float* vcol = vph + toff[t];
#pragma unroll
                for (int c = 0; c < 16; ++c) acc[c] += pw * vcol[(size_t)c * PP];
            }
        }
        uint4* dh = reinterpret_cast<uint4*>(g_yh + p * 256 + qc + half * 16);
        uint4* dl = reinterpret_cast<uint4*>(g_yl + p * 256 + qc + half * 16);
#pragma unroll
        for (int qd = 0; qd < 2; ++qd) {
            uint32_t hx[4], lx[4];
#pragma unroll
            for (int e = 0; e < 4; ++e) {
                const float f0 = acc[qd * 8 + e * 2];
                const float f1 = acc[qd * 8 + e * 2 + 1];
                const float h0 = __bfloat162float(__float2bfloat16(f0));
                const float h1 = __bfloat162float(__float2bfloat16(f1));
                hx[e] = pk2(f0, f1);
                lx[e] = pk2(f0 - h0, f1 - h1);
            }
            dh[qd] = make_uint4(hx[0], hx[1], hx[2], hx[3]);
            dl[qd] = make_uint4(lx[0], lx[1], lx[2], lx[3]);
        }
    }
}

// ---------------------------------------------------------------------------
// Kernel 5: per-(b,c) 64x64 @ 64x64 matmul: o = vi[b,c] @ div[b,c].
// g_div layout is [c][b*4096 + n].
// ---------------------------------------------------------------------------
__global__ __launch_bounds__(256)
void k_final(const float* __restrict__ vi, float* __restrict__ out, int dup)
{
    const int bc = blockIdx.x;
    const int b = bc >> 8, c = bc & 255;
    const float* __restrict__ Ap = vi    + (size_t)bc * 4096;
    const float* __restrict__ Bp = g_div + (size_t)c * PP + (size_t)b * NN;

    __shared__ __align__(16) float Asm[64][68];  // transposed
    __shared__ __align__(16) float Bsm[64][64];

    const int t  = threadIdx.x;
    const int tx = t & 15, ty = t >> 4;

#pragma unroll
    for (int it = 0; it < 4; ++it) {
        const int e  = t + 256 * it;
        const int r  = e >> 4;
        const int c4 = (e & 15) * 4;
        const float4 a4 = *reinterpret_cast<const float4*>(Ap + r * 64 + c4);
        Asm[c4 + 0][r] = a4.x; Asm[c4 + 1][r] = a4.y;
        Asm[c4 + 2][r] = a4.z; Asm[c4 + 3][r] = a4.w;
        *reinterpret_cast<float4*>(&Bsm[r][c4]) =
            *reinterpret_cast<const float4*>(Bp + r * 64 + c4);
    }
    __syncthreads();

    float acc[4][4] = {};
#pragma unroll
    for (int k = 0; k < 64; ++k) {
        float a_[4], b_[4];
#pragma unroll
        for (int i = 0; i < 4; ++i) a_[i] = Asm[k][ty * 4 + i];
#pragma unroll
        for (int j = 0; j < 4; ++j) b_[j] = Bsm[k][tx * 4 + j];
#pragma unroll
        for (int i = 0; i < 4; ++i)
#pragma unroll
            for (int j = 0; j < 4; ++j)
                acc[i][j] += a_[i] * b_[j];
    }

#pragma unroll
    for (int i = 0; i < 4; ++i) {
        const size_t idx = (size_t)bc * 4096 + (size_t)(ty * 4 + i) * 64 + tx * 4;
        const float4 v = make_float4(acc[i][0], acc[i][1], acc[i][2], acc[i][3]);
        *reinterpret_cast<float4*>(out + idx) = v;
        if (dup) *reinterpret_cast<float4*>(out + (size_t)NUMEL + idx) = v;
    }
}

// ---------------------------------------------------------------------------
extern "C" void kernel_launch(void* const* d_in, const int* in_sizes, int n_in,
                              void* d_out, int out_size)
{
    const float* vi     = (const float*)d_in[0];
    const float* ir     = (const float*)d_in[1];
    const float* w_qkv  = (const float*)d_in[2];
    const float* proj_w = (const float*)d_in[3];
    const float* proj_b = (const float*)d_in[4];
    const float* ln_g   = (const float*)d_in[5];
    const float* ln_b   = (const float*)d_in[6];
    float* out = (float*)d_out;

    const int dup = (out_size >= 2 * NUMEL) ? 1 : 0;
    const int SMEM_GEMM = 2 * STAGE_B;   // 81920 B

    static bool attr_done = false;
    if (!attr_done) {
        cudaFuncSetAttribute(k_gemm_mma<0>, cudaFuncAttributeMaxDynamicSharedMemorySize, SMEM_GEMM);
        cudaFuncSetAttribute(k_gemm_mma<1>, cudaFuncAttributeMaxDynamicSharedMemorySize, SMEM_GEMM);
        attr_done = true;
    }

    // 0. weight bf16 split
    k_wsplit<<<1024, 256>>>(w_qkv, proj_w);
    // 1. sub + LN -> Xt hi/lo (transposed bf16 split)
    k_subln<<<dim3(NN / 32, BB), dim3(32, 8)>>>(vi, ir, ln_g, ln_b);
    // 2. QKV GEMM (HMMA): g_qkv[768][32768]
    k_gemm_mma<0><<<dim3(PP / 128, 6), 256, SMEM_GEMM>>>(nullptr, nullptr, nullptr);
    // 3. dilated local attention -> Yt hi/lo
    k_attn<<<dim3(NN / 256, 8, BB), 256>>>();
    // 4. proj GEMM (HMMA) + bias + residual -> g_div[256][32768]
    k_gemm_mma<1><<<dim3(PP / 128, 2), 256, SMEM_GEMM>>>(proj_b, vi, ir);
    // 5. batched 64x64 matmul: out = vi @ div, duplicated
    k_final<<<BB * CC, 256>>>(vi, out, dup);
}

// round 16
// speedup vs baseline: 1.1157x; 1.0067x over previous
#include <cuda_runtime.h>
#include <cuda_bf16.h>
#include <math.h>
#include <stdint.h>

// Problem constants
#define BB   8
#define CC   256
#define NN   4096          // H*W
#define PP   32768         // B*N fused pixel index
#define NUMEL (BB*CC*NN)   // 8388608

__constant__ int c_dil[4] = {1, 2, 3, 4};
constexpr float SCALE_F = 0.17677669529663687f; // 32^-0.5
constexpr float EPS_F   = 1e-5f;

// ---------------------------------------------------------------------------
// Static device scratch (no runtime allocation)
// ---------------------------------------------------------------------------
__device__ __align__(16) __nv_bfloat16 g_xh[PP * 256];
__device__ __align__(16) __nv_bfloat16 g_xl[PP * 256];
__device__ __align__(16) __nv_bfloat16 g_yh[PP * 256];
__device__ __align__(16) __nv_bfloat16 g_yl[PP * 256];
__device__ __align__(16) __nv_bfloat16 g_wh[1024 * 256];
__device__ __align__(16) __nv_bfloat16 g_wl[1024 * 256];
__device__ __align__(16) float         g_qkv[256 * PP];   // Q rows, fp32 (33 MB)
__device__ __align__(16) __nv_bfloat16 g_kvb[512 * PP];   // K,V rows, bf16 (33 MB)
__device__ __align__(16) float         g_div[256 * PP];

// ---------------------------------------------------------------------------
// PTX helpers (sm_103-safe: no 'a'-only features)
// ---------------------------------------------------------------------------
__device__ __forceinline__ uint32_t cvta_smem(const void* p) {
    uint32_t a;
    asm("{ .reg .u64 t; cvta.to.shared.u64 t, %1; cvt.u32.u64 %0, t; }"
        : "=r"(a) : "l"(p));
    return a;
}

#define LDM4(r, a) \
    asm volatile("ldmatrix.sync.aligned.m8n8.x4.shared.b16 {%0,%1,%2,%3}, [%4];" \
        : "=r"((r)[0]), "=r"((r)[1]), "=r"((r)[2]), "=r"((r)[3]) : "r"(a))

#define MMA_BF16(c, a, b0_, b1_) \
    asm volatile("mma.sync.aligned.m16n8k16.row.col.f32.bf16.bf16.f32 " \
        "{%0,%1,%2,%3}, {%4,%5,%6,%7}, {%8,%9}, {%0,%1,%2,%3};" \
        : "+f"((c)[0]), "+f"((c)[1]), "+f"((c)[2]), "+f"((c)[3]) \
        : "r"((a)[0]), "r"((a)[1]), "r"((a)[2]), "r"((a)[3]), "r"(b0_), "r"(b1_))

#define CP_ASYNC16(sa, gp) \
    asm volatile("{ .reg .u64 ga; cvta.to.global.u64 ga, %1; " \
                 "cp.async.cg.shared.global [%0], [ga], 16; }" \
        :: "r"(sa), "l"(gp) : "memory")

#define CP_COMMIT() asm volatile("cp.async.commit_group;" ::: "memory")

__device__ __forceinline__ uint32_t pk2(float a, float b) {
    __nv_bfloat162 h = __floats2bfloat162_rn(a, b);
    return *reinterpret_cast<uint32_t*>(&h);
}

// ---------------------------------------------------------------------------
// Kernel W-split: bf16 hi/lo of [w_qkv ; proj_w] (1024 x 256)
// ---------------------------------------------------------------------------
__global__ __launch_bounds__(256)
void k_wsplit(const float* __restrict__ wq, const float* __restrict__ pw)
{
    const int i = blockIdx.x * 256 + threadIdx.x;
    if (i >= 1024 * 256) return;
    const float v = (i < 768 * 256) ? wq[i] : pw[i - 768 * 256];
    const __nv_bfloat16 h = __float2bfloat16(v);
    g_wh[i] = h;
    g_wl[i] = __float2bfloat16(v - __bfloat162float(h));
}

// ---------------------------------------------------------------------------
// Kernel 1: sub + LayerNorm over C, emitting bf16 hi/lo TRANSPOSED: Xt[p][k].
// ---------------------------------------------------------------------------
__global__ __launch_bounds__(256)
void k_subln(const float* __restrict__ vi, const float* __restrict__ ir,
             const float* __restrict__ ln_g, const float* __restrict__ ln_b)
{
    const int b    = blockIdx.y;
    const int pix0 = blockIdx.x * 32;
    const int tx = threadIdx.x, ty = threadIdx.y;
    const int n  = pix0 + tx;
    const size_t base = (size_t)b * CC * NN + n;

    __shared__ float s_t[32 * 257];           // [pixel][channel]
    __shared__ float s_sum[8][32], s_sq[8][32];
    __shared__ float s_mean[32], s_rstd[32];

    float vals[32];
    float s = 0.f, s2 = 0.f;
#pragma unroll
    for (int u = 0; u < 32; ++u) {
        const int c = ty + u * 8;
        const float v = vi[base + (size_t)c * NN] - ir[base + (size_t)c * NN];
        vals[u] = v; s += v; s2 += v * v;
    }
    s_sum[ty][tx] = s; s_sq[ty][tx] = s2;
    __syncthreads();
    if (ty == 0) {
        float tot = 0.f, tot2 = 0.f;
#pragma unroll
        for (int u = 0; u < 8; ++u) { tot += s_sum[u][tx]; tot2 += s_sq[u][tx]; }
        const float mean = tot * (1.0f / CC);
        const float var  = tot2 * (1.0f / CC) - mean * mean;
        s_mean[tx] = mean;
        s_rstd[tx] = rsqrtf(var + EPS_F);
    }
    __syncthreads();
    const float mean = s_mean[tx], rstd = s_rstd[tx];
#pragma unroll
    for (int u = 0; u < 32; ++u) {
        const int c = ty + u * 8;
        s_t[tx * 257 + c] = (vals[u] - mean) * rstd * ln_g[c] + ln_b[c];
    }
    __syncthreads();

    // transposed, coalesced bf16 hi/lo emission
    const int tt = ty * 32 + tx;
    const int pl = tt >> 3;
    const int c0 = (tt & 7) * 32;
    const size_t p = (size_t)b * NN + pix0 + pl;
    const float* row = &s_t[pl * 257 + c0];
    uint4* dh = reinterpret_cast<uint4*>(g_xh + p * 256 + c0);
    uint4* dl = reinterpret_cast<uint4*>(g_xl + p * 256 + c0);
#pragma unroll
    for (int q = 0; q < 4; ++q) {
        uint32_t hx[4], lx[4];
#pragma unroll
        for (int e = 0; e < 4; ++e) {
            const float f0 = row[q * 8 + e * 2];
            const float f1 = row[q * 8 + e * 2 + 1];
            const float h0 = __bfloat162float(__float2bfloat16(f0));
            const float h1 = __bfloat162float(__float2bfloat16(f1));
            hx[e] = pk2(f0, f1);
            lx[e] = pk2(f0 - h0, f1 - h1);
        }
        dh[q] = make_uint4(hx[0], hx[1], hx[2], hx[3]);
        dl[q] = make_uint4(lx[0], lx[1], lx[2], lx[3]);
    }
}

// ---------------------------------------------------------------------------
// HMMA bf16-split GEMM: C[m][p] = sum_k A[m][k] * X[k][p], K=256.
// CTA tile 128x128, BK=32, 256 threads (8 warps, 4m x 2n), warp tile 32x64.
// 3-term split: C = Ah*Bh + Al*Bh + Ah*Bl (fp32 accumulate).
// MODE 0: rows < 256 -> fp32 g_qkv (Q); rows >= 256 -> bf16 g_kvb (K,V).
// MODE 1: proj rows, epi += bias + vi - ir, fp32 g_div.
// ---------------------------------------------------------------------------
#define TILE_B   10240     // 128 rows * 80 B
#define STAGE_B  40960     // 4 tiles
template <int MODE>
__global__ __launch_bounds__(256, 2)
void k_gemm_mma(const float* __restrict__ bias,
                const float* __restrict__ vi,
                const float* __restrict__ ir)
{
    extern __shared__ char smem[];
    const uint32_t sb = cvta_smem(smem);
    const int t    = threadIdx.x;
    const int lane = t & 31, wid = t >> 5;
    const int p0 = blockIdx.x * 128;
    const int m0 = blockIdx.y * 128;
    const int arow0 = (MODE == 0 ? 0 : 768) + m0;

    const __nv_bfloat16* __restrict__ Bh = (MODE == 0 ? g_xh : g_yh);
    const __nv_bfloat16* __restrict__ Bl = (MODE == 0 ? g_xl : g_yl);

    // ---- global->smem load mapping: 4 tau groups of 64 threads ----
    const int tau = t >> 6, sub = t & 63;
    const __nv_bfloat16* __restrict__ gsrc =
        (tau == 0) ? g_wh + (size_t)arow0 * 256 :
        (tau == 1) ? g_wl + (size_t)arow0 * 256 :
        (tau == 2) ? Bh + (size_t)p0 * 256 :
                     Bl + (size_t)p0 * 256;
    const uint32_t s_tile = sb + tau * TILE_B;

    // ---- fragment lane constants ----
    const int matq = lane >> 3, l7 = lane & 7;
    const int aRow = ((matq & 1) << 3) + l7;      // row within 16
    const int aK   = (matq >> 1) << 3;            // k within 16
    const int bRow = ((matq >> 1) << 3) + l7;
    const int bK   = (matq & 1) << 3;
    const int warp_m = wid >> 1, warp_n = wid & 1;
    const int mb = warp_m * 32, nb = warp_n * 64;
    const uint32_t aOffB = (uint32_t)(mb + aRow) * 80 + aK * 2;
    const uint32_t bOffB = (uint32_t)(nb + bRow) * 80 + bK * 2;

    float acc[2][8][4] = {};

    // ---- prologue: issue chunk 0 ----
    {
        const uint32_t sdst0 = s_tile;
#pragma unroll
        for (int it = 0; it < 8; ++it) {
            const int seg = sub + it * 64;
            const int row = seg >> 2, ks = seg & 3;
            const __nv_bfloat16* gp = gsrc + (size_t)row * 256 + ks * 8;
            CP_ASYNC16(sdst0 + row * 80 + ks * 16, gp);
        }
        CP_COMMIT();
    }

    for (int ch = 0; ch < 8; ++ch) {
        if (ch < 7) {
            const int kc = (ch + 1) * 32;
            const uint32_t sdst0 = s_tile + ((ch + 1) & 1) * STAGE_B;
#pragma unroll
            for (int it = 0; it < 8; ++it) {
                const int seg = sub + it * 64;
                const int row = seg >> 2, ks = seg & 3;
                const __nv_bfloat16* gp = gsrc + (size_t)row * 256 + kc + ks * 8;
                CP_ASYNC16(sdst0 + row * 80 + ks * 16, gp);
            }
            CP_COMMIT();
            asm volatile("cp.async.wait_group 1;" ::: "memory");
        } else {
            asm volatile("cp.async.wait_group 0;" ::: "memory");
        }
        __syncthreads();

        const uint32_t st = sb + (ch & 1) * STAGE_B;
#pragma unroll
        for (int kk2 = 0; kk2 < 2; ++kk2) {
            const uint32_t kB = kk2 * 32;        // 16 bf16 = 32 bytes
            uint32_t ah[2][4], al[2][4];
#pragma unroll
            for (int i = 0; i < 2; ++i) {
                LDM4(ah[i], st + 0 * TILE_B + aOffB + i * 1280 + kB);
                LDM4(al[i], st + 1 * TILE_B + aOffB + i * 1280 + kB);
            }
#pragma unroll
            for (int j = 0; j < 4; ++j) {
                uint32_t bh[4], bl[4];
                LDM4(bh, st + 2 * TILE_B + bOffB + j * 1280 + kB);
                LDM4(bl, st + 3 * TILE_B + bOffB + j * 1280 + kB);
#pragma unroll
                for (int i = 0; i < 2; ++i)
#pragma unroll
                    for (int h = 0; h < 2; ++h) {
                        const int jn = j * 2 + h;
                        MMA_BF16(acc[i][jn], ah[i], bh[h*2], bh[h*2+1]);
                        MMA_BF16(acc[i][jn], al[i], bh[h*2], bh[h*2+1]);
                        MMA_BF16(acc[i][jn], ah[i], bl[h*2], bl[h*2+1]);
                    }
            }
        }
        __syncthreads();
    }

    // ---- epilogue ----
    const int g  = lane >> 2, tg = lane & 3;
    const int b  = p0 >> 12;          // N tile lies within one batch image
    const int n0 = p0 & 4095;
#pragma unroll
    for (int i = 0; i < 2; ++i) {
#pragma unroll
        for (int r = 0; r < 2; ++r) {
            const int m = m0 + mb + i * 16 + r * 8 + g;
            if (MODE == 0) {
                if (m < 256) {   // Q rows: fp32
                    float* crow = g_qkv + (size_t)m * PP + p0;
#pragma unroll
                    for (int jn = 0; jn < 8; ++jn) {
                        const int col = nb + jn * 8 + tg * 2;
                        *reinterpret_cast<float2*>(crow + col) =
                            make_float2(acc[i][jn][r*2], acc[i][jn][r*2+1]);
                    }
                } else {         // K,V rows: bf16
                    __nv_bfloat16* krow = g_kvb + (size_t)(m - 256) * PP + p0;
#pragma unroll
                    for (int jn = 0; jn < 8; ++jn) {
                        const int col = nb + jn * 8 + tg * 2;
                        *reinterpret_cast<uint32_t*>(krow + col) =
                            pk2(acc[i][jn][r*2], acc[i][jn][r*2+1]);
                    }
                }
            } else {
                float* crow = g_div + (size_t)m * PP + p0;
                const float bb = bias[m];
                const float* vrow = vi + ((size_t)b * CC + m) * NN + n0;
                const float* irow = ir + ((size_t)b * CC + m) * NN + n0;
#pragma unroll
                for (int jn = 0; jn < 8; ++jn) {
                    const int col = nb + jn * 8 + tg * 2;
                    float2 v = make_float2(acc[i][jn][r*2], acc[i][jn][r*2+1]);
                    const float2 rv = *reinterpret_cast<const float2*>(vrow + col);
                    const float2 ri = *reinterpret_cast<const float2*>(irow + col);
                    v.x += bb + rv.x - ri.x;
                    v.y += bb + rv.y - ri.y;
                    *reinterpret_cast<float2*>(crow + col) = v;
                }
            }
        }
    }
}

// ---------------------------------------------------------------------------
// Kernel 3: dilated local attention. One thread per (b, head, pixel).
// Channels in 4 quarter-passes of 8 (low regs, full 32-pixel coalescing).
// Q fp32, K/V bf16. grid (NN/256, 8 heads, BB), block 256.
// ---------------------------------------------------------------------------
__global__ __launch_bounds__(256)
void k_attn()
{
    const int b  = blockIdx.z;
    const int hg = blockIdx.y;               // global head 0..7
    const int n  = blockIdx.x * 256 + threadIdx.x;
    const int g  = hg >> 1;                  // dilation group
    const int dil = c_dil[g];
    const int qc = g * 64 + (hg & 1) * 32;   // channel base within 256

    const float* __restrict__ qp = g_qkv + (size_t)qc * PP + (size_t)b * NN;
    const __nv_bfloat16* __restrict__ kp = g_kvb + (size_t)qc * PP + (size_t)b * NN;
    const __nv_bfloat16* __restrict__ vp = g_kvb + (size_t)(256 + qc) * PP + (size_t)b * NN;

    const int yy = n >> 6, xx = n & 63;

    // tap geometry (precompute validity + offset once)
    int   toff[9];
    bool  tok[9];
#pragma unroll
    for (int t = 0; t < 9; ++t) {
        const int py = yy + (t / 3 - 1) * dil;
        const int px = xx + (t % 3 - 1) * dil;
        tok[t]  = ((unsigned)py < 64u) && ((unsigned)px < 64u);
        toff[t] = py * 64 + px;
    }

    // ---- Pass A: logits over 4 channel quarters ----
    float logit[9] = {0.f, 0.f, 0.f, 0.f, 0.f, 0.f, 0.f, 0.f, 0.f};
#pragma unroll
    for (int qt = 0; qt < 4; ++qt) {
        const float* qph = qp + (size_t)(qt * 8) * PP;
        const __nv_bfloat16* kph = kp + (size_t)(qt * 8) * PP;
        float q[8];
#pragma unroll
        for (int c = 0; c < 8; ++c) q[c] = qph[(size_t)c * PP + n];
#pragma unroll
        for (int t = 0; t < 9; ++t) {
            if (tok[t]) {
                const __nv_bfloat16* kcol = kph + toff[t];
                float s = 0.f;
#pragma unroll
                for (int c = 0; c < 8; ++c)
                    s += q[c] * __bfloat162float(kcol[(size_t)c * PP]);
                logit[t] += s;
            }
        }
    }

    float mx = -1e30f;
#pragma unroll
    for (int t = 0; t < 9; ++t) {
        logit[t] *= SCALE_F;       // zero-padded taps give exactly 0 (matches Unfold)
        mx = fmaxf(mx, logit[t]);
    }
    float den = 0.f;
#pragma unroll
    for (int t = 0; t < 9; ++t) { logit[t] = expf(logit[t] - mx); den += logit[t]; }
    const float inv = 1.0f / den;
#pragma unroll
    for (int t = 0; t < 9; ++t) logit[t] *= inv;

    // ---- Pass B: AV per quarter, write out immediately ----
    const size_t p = (size_t)b * NN + n;
#pragma unroll
    for (int qt = 0; qt < 4; ++qt) {
        const __nv_bfloat16* vph = vp + (size_t)(qt * 8) * PP;
        float acc[8] = {};
#pragma unroll
        for (int t = 0; t < 9; ++t) {
            if (tok[t]) {
                const float pw = logit[t];
                const __nv_bfloat16* vcol = vph + toff[t];
#pragma unroll
                for (int c = 0; c < 8; ++c)
                    acc[c] += pw * __bfloat162float(vcol[(size_t)c * PP]);
            }
        }
        uint32_t hx[4], lx[4];
#pragma unroll
        for (int e = 0; e < 4; ++e) {
            const float f0 = acc[e * 2];
            const float f1 = acc[e * 2 + 1];
            const float h0 = __bfloat162float(__float2bfloat16(f0));
            const float h1 = __bfloat162float(__float2bfloat16(f1));
            hx[e] = pk2(f0, f1);
            lx[e] = pk2(f0 - h0, f1 - h1);
        }
        *reinterpret_cast<uint4*>(g_yh + p * 256 + qc + qt * 8) =
            make_uint4(hx[0], hx[1], hx[2], hx[3]);
        *reinterpret_cast<uint4*>(g_yl + p * 256 + qc + qt * 8) =
            make_uint4(lx[0], lx[1], lx[2], lx[3]);
    }
}

// ---------------------------------------------------------------------------
// Kernel 5: per-(b,c) 64x64 @ 64x64 matmul: o = vi[b,c] @ div[b,c].
// g_div layout is [c][b*4096 + n].
// ---------------------------------------------------------------------------
__global__ __launch_bounds__(256)
void k_final(const float* __restrict__ vi, float* __restrict__ out, int dup)
{
    const int bc = blockIdx.x;
    const int b = bc >> 8, c = bc & 255;
    const float* __restrict__ Ap = vi    + (size_t)bc * 4096;
    const float* __restrict__ Bp = g_div + (size_t)c * PP + (size_t)b * NN;

    __shared__ __align__(16) float Asm[64][68];  // transposed
    __shared__ __align__(16) float Bsm[64][64];

    const int t  = threadIdx.x;
    const int tx = t & 15, ty = t >> 4;

#pragma unroll
    for (int it = 0; it < 4; ++it) {
        const int e  = t + 256 * it;
        const int r  = e >> 4;
        const int c4 = (e & 15) * 4;
        const float4 a4 = *reinterpret_cast<const float4*>(Ap + r * 64 + c4);
        Asm[c4 + 0][r] = a4.x; Asm[c4 + 1][r] = a4.y;
        Asm[c4 + 2][r] = a4.z; Asm[c4 + 3][r] = a4.w;
        *reinterpret_cast<float4*>(&Bsm[r][c4]) =
            *reinterpret_cast<const float4*>(Bp + r * 64 + c4);
    }
    __syncthreads();

    float acc[4][4] = {};
#pragma unroll
    for (int k = 0; k < 64; ++k) {
        float a_[4], b_[4];
#pragma unroll
        for (int i = 0; i < 4; ++i) a_[i] = Asm[k][ty * 4 + i];
#pragma unroll
        for (int j = 0; j < 4; ++j) b_[j] = Bsm[k][tx * 4 + j];
#pragma unroll
        for (int i = 0; i < 4; ++i)
#pragma unroll
            for (int j = 0; j < 4; ++j)
                acc[i][j] += a_[i] * b_[j];
    }

#pragma unroll
    for (int i = 0; i < 4; ++i) {
        const size_t idx = (size_t)bc * 4096 + (size_t)(ty * 4 + i) * 64 + tx * 4;
        const float4 v = make_float4(acc[i][0], acc[i][1], acc[i][2], acc[i][3]);
        *reinterpret_cast<float4*>(out + idx) = v;
        if (dup) *reinterpret_cast<float4*>(out + (size_t)NUMEL + idx) = v;
    }
}

// ---------------------------------------------------------------------------
extern "C" void kernel_launch(void* const* d_in, const int* in_sizes, int n_in,
                              void* d_out, int out_size)
{
    const float* vi     = (const float*)d_in[0];
    const float* ir     = (const float*)d_in[1];
    const float* w_qkv  = (const float*)d_in[2];
    const float* proj_w = (const float*)d_in[3];
    const float* proj_b = (const float*)d_in[4];
    const float* ln_g   = (const float*)d_in[5];
    const float* ln_b   = (const float*)d_in[6];
    float* out = (float*)d_out;

    const int dup = (out_size >= 2 * NUMEL) ? 1 : 0;
    const int SMEM_GEMM = 2 * STAGE_B;   // 81920 B

    static bool attr_done = false;
    if (!attr_done) {
        cudaFuncSetAttribute(k_gemm_mma<0>, cudaFuncAttributeMaxDynamicSharedMemorySize, SMEM_GEMM);
        cudaFuncSetAttribute(k_gemm_mma<1>, cudaFuncAttributeMaxDynamicSharedMemorySize, SMEM_GEMM);
        attr_done = true;
    }

    // 0. weight bf16 split
    k_wsplit<<<1024, 256>>>(w_qkv, proj_w);
    // 1. sub + LN -> Xt hi/lo (transposed bf16 split)
    k_subln<<<dim3(NN / 32, BB), dim3(32, 8)>>>(vi, ir, ln_g, ln_b);
    // 2. QKV GEMM (HMMA): Q fp32 + K,V bf16
    k_gemm_mma<0><<<dim3(PP / 128, 6), 256, SMEM_GEMM>>>(nullptr, nullptr, nullptr);
    // 3. dilated local attention -> Yt hi/lo
    k_attn<<<dim3(NN / 256, 8, BB), 256>>>();
    // 4. proj GEMM (HMMA) + bias + residual -> g_div[256][32768]
    k_gemm_mma<1><<<dim3(PP / 128, 2), 256, SMEM_GEMM>>>(proj_b, vi, ir);
    // 5. batched 64x64 matmul: out = vi @ div, duplicated
    k_final<<<BB * CC, 256>>>(vi, out, dup);
}

// round 17
// speedup vs baseline: 1.2756x; 1.1433x over previous
#include <cuda_runtime.h>
#include <cuda_bf16.h>
#include <math.h>
#include <stdint.h>

// Problem constants
#define BB   8
#define CC   256
#define NN   4096          // H*W
#define PP   32768         // B*N fused pixel index
#define NUMEL (BB*CC*NN)   // 8388608

__constant__ int c_dil[4] = {1, 2, 3, 4};
constexpr float SCALE_F = 0.17677669529663687f; // 32^-0.5
constexpr float EPS_F   = 1e-5f;

// ---------------------------------------------------------------------------
// Static device scratch (no runtime allocation)
// ---------------------------------------------------------------------------
__device__ __align__(16) __nv_bfloat16 g_xh[PP * 256];    // LN out hi, [p][k]
__device__ __align__(16) __nv_bfloat16 g_yh[PP * 256];    // attn out hi, [p][k]
__device__ __align__(16) __nv_bfloat16 g_yl[PP * 256];    // attn out lo, [p][k]
__device__ __align__(16) __nv_bfloat16 g_wh[1024 * 256];  // weights hi
__device__ __align__(16) __nv_bfloat16 g_wl[1024 * 256];  // weights lo
__device__ __align__(16) __nv_bfloat16 g_qkv[768 * PP];   // Q,K,V all bf16 (50 MB)
__device__ __align__(16) float         g_div[256 * PP];

// ---------------------------------------------------------------------------
// PTX helpers (sm_103-safe: no 'a'-only features)
// ---------------------------------------------------------------------------
__device__ __forceinline__ uint32_t cvta_smem(const void* p) {
    uint32_t a;
    asm("{ .reg .u64 t; cvta.to.shared.u64 t, %1; cvt.u32.u64 %0, t; }"
        : "=r"(a) : "l"(p));
    return a;
}

#define LDM4(r, a) \
    asm volatile("ldmatrix.sync.aligned.m8n8.x4.shared.b16 {%0,%1,%2,%3}, [%4];" \
        : "=r"((r)[0]), "=r"((r)[1]), "=r"((r)[2]), "=r"((r)[3]) : "r"(a))

#define MMA_BF16(c, a, b0_, b1_) \
    asm volatile("mma.sync.aligned.m16n8k16.row.col.f32.bf16.bf16.f32 " \
        "{%0,%1,%2,%3}, {%4,%5,%6,%7}, {%8,%9}, {%0,%1,%2,%3};" \
        : "+f"((c)[0]), "+f"((c)[1]), "+f"((c)[2]), "+f"((c)[3]) \
        : "r"((a)[0]), "r"((a)[1]), "r"((a)[2]), "r"((a)[3]), "r"(b0_), "r"(b1_))

#define CP_ASYNC16(sa, gp) \
    asm volatile("{ .reg .u64 ga; cvta.to.global.u64 ga, %1; " \
                 "cp.async.cg.shared.global [%0], [ga], 16; }" \
        :: "r"(sa), "l"(gp) : "memory")

#define CP_COMMIT() asm volatile("cp.async.commit_group;" ::: "memory")

__device__ __forceinline__ uint32_t pk2(float a, float b) {
    __nv_bfloat162 h = __floats2bfloat162_rn(a, b);
    return *reinterpret_cast<uint32_t*>(&h);
}

// ---------------------------------------------------------------------------
// Kernel W-split: bf16 hi/lo of [w_qkv ; proj_w] (1024 x 256)
// ---------------------------------------------------------------------------
__global__ __launch_bounds__(256)
void k_wsplit(const float* __restrict__ wq, const float* __restrict__ pw)
{
    const int i = blockIdx.x * 256 + threadIdx.x;
    if (i >= 1024 * 256) return;
    const float v = (i < 768 * 256) ? wq[i] : pw[i - 768 * 256];
    const __nv_bfloat16 h = __float2bfloat16(v);
    g_wh[i] = h;
    g_wl[i] = __float2bfloat16(v - __bfloat162float(h));
}

// ---------------------------------------------------------------------------
// Kernel 1: sub + LayerNorm over C, emitting bf16 hi TRANSPOSED: Xt[p][k].
// ---------------------------------------------------------------------------
__global__ __launch_bounds__(256)
void k_subln(const float* __restrict__ vi, const float* __restrict__ ir,
             const float* __restrict__ ln_g, const float* __restrict__ ln_b)
{
    const int b    = blockIdx.y;
    const int pix0 = blockIdx.x * 32;
    const int tx = threadIdx.x, ty = threadIdx.y;
    const int n  = pix0 + tx;
    const size_t base = (size_t)b * CC * NN + n;

    __shared__ float s_t[32 * 257];           // [pixel][channel]
    __shared__ float s_sum[8][32], s_sq[8][32];
    __shared__ float s_mean[32], s_rstd[32];

    float vals[32];
    float s = 0.f, s2 = 0.f;
#pragma unroll
    for (int u = 0; u < 32; ++u) {
        const int c = ty + u * 8;
        const float v = vi[base + (size_t)c * NN] - ir[base + (size_t)c * NN];
        vals[u] = v; s += v; s2 += v * v;
    }
    s_sum[ty][tx] = s; s_sq[ty][tx] = s2;
    __syncthreads();
    if (ty == 0) {
        float tot = 0.f, tot2 = 0.f;
#pragma unroll
        for (int u = 0; u < 8; ++u) { tot += s_sum[u][tx]; tot2 += s_sq[u][tx]; }
        const float mean = tot * (1.0f / CC);
        const float var  = tot2 * (1.0f / CC) - mean * mean;
        s_mean[tx] = mean;
        s_rstd[tx] = rsqrtf(var + EPS_F);
    }
    __syncthreads();
    const float mean = s_mean[tx], rstd = s_rstd[tx];
#pragma unroll
    for (int u = 0; u < 32; ++u) {
        const int c = ty + u * 8;
        s_t[tx * 257 + c] = (vals[u] - mean) * rstd * ln_g[c] + ln_b[c];
    }
    __syncthreads();

    // transposed, coalesced bf16 hi emission: thread -> (pixel, 32 channels)
    const int tt = ty * 32 + tx;
    const int pl = tt >> 3;
    const int c0 = (tt & 7) * 32;
    const size_t p = (size_t)b * NN + pix0 + pl;
    const float* row = &s_t[pl * 257 + c0];
    uint4* dh = reinterpret_cast<uint4*>(g_xh + p * 256 + c0);
#pragma unroll
    for (int q = 0; q < 4; ++q) {
        uint32_t hx[4];
#pragma unroll
        for (int e = 0; e < 4; ++e)
            hx[e] = pk2(row[q * 8 + e * 2], row[q * 8 + e * 2 + 1]);
        dh[q] = make_uint4(hx[0], hx[1], hx[2], hx[3]);
    }
}

// ---------------------------------------------------------------------------
// HMMA bf16-split GEMM: C[m][p] = sum_k A[m][k] * X[k][p], K=256.
// CTA tile 128x128, BK=32, 256 threads (8 warps, 4m x 2n), warp tile 32x64.
// MODE 0 (QKV): 2-term split C = Ah*Bh + Al*Bh, B = Xh only (3 smem tiles);
//               output all-bf16 g_qkv.
// MODE 1 (proj): 3-term split (4 tiles, B = Yh,Yl), fp32 out,
//               epi += bias + vi - ir.
// ---------------------------------------------------------------------------
#define TILE_B   10240     // 128 rows * 80 B
template <int MODE>
__global__ __launch_bounds__(256, 2)
void k_gemm_mma(const float* __restrict__ bias,
                const float* __restrict__ vi,
                const float* __restrict__ ir)
{
    constexpr int NTILES = (MODE == 0) ? 3 : 4;
    constexpr uint32_t STAGE = NTILES * TILE_B;

    extern __shared__ char smem[];
    const uint32_t sb = cvta_smem(smem);
    const int t    = threadIdx.x;
    const int lane = t & 31, wid = t >> 5;
    const int p0 = blockIdx.x * 128;
    const int m0 = blockIdx.y * 128;
    const int arow0 = (MODE == 0 ? 0 : 768) + m0;

    const __nv_bfloat16* __restrict__ src0 = g_wh + (size_t)arow0 * 256;
    const __nv_bfloat16* __restrict__ src1 = g_wl + (size_t)arow0 * 256;
    const __nv_bfloat16* __restrict__ src2 =
        (MODE == 0 ? g_xh : g_yh) + (size_t)p0 * 256;
    const __nv_bfloat16* __restrict__ src3 =
        (MODE == 0 ? g_yl : g_yl) + (size_t)p0 * 256;  // unused in MODE 0

    // ---- fragment lane constants ----
    const int matq = lane >> 3, l7 = lane & 7;
    const int aRow = ((matq & 1) << 3) + l7;
    const int aK   = (matq >> 1) << 3;
    const int bRow = ((matq >> 1) << 3) + l7;
    const int bK   = (matq & 1) << 3;
    const int warp_m = wid >> 1, warp_n = wid & 1;
    const int mb = warp_m * 32, nb = warp_n * 64;
    const uint32_t aOffB = (uint32_t)(mb + aRow) * 80 + aK * 2;
    const uint32_t bOffB = (uint32_t)(nb + bRow) * 80 + bK * 2;

    float acc[2][8][4] = {};

    // ---- load issuer: NTILES tiles, 512 x 16B ops each, 2 its per tile ----
    auto issue = [&](int kc, uint32_t sbase) {
#pragma unroll
        for (int it = 0; it < NTILES * 2; ++it) {
            const int tile = it >> 1;
            const int seg  = t + (it & 1) * 256;
            const int row  = seg >> 2, ks = seg & 3;
            const __nv_bfloat16* s =
                (tile == 0) ? src0 : (tile == 1) ? src1 : (tile == 2) ? src2 : src3;
            CP_ASYNC16(sbase + tile * TILE_B + row * 80 + ks * 16,
                       s + (size_t)row * 256 + kc + ks * 8);
        }
        CP_COMMIT();
    };

    issue(0, sb);

    for (int ch = 0; ch < 8; ++ch) {
        if (ch < 7) {
            issue((ch + 1) * 32, sb + ((ch + 1) & 1) * STAGE);
            asm volatile("cp.async.wait_group 1;" ::: "memory");
        } else {
            asm volatile("cp.async.wait_group 0;" ::: "memory");
        }
        __syncthreads();

        const uint32_t st = sb + (ch & 1) * STAGE;
#pragma unroll
        for (int kk2 = 0; kk2 < 2; ++kk2) {
            const uint32_t kB = kk2 * 32;        // 16 bf16 = 32 bytes
            uint32_t ah[2][4], al[2][4];
#pragma unroll
            for (int i = 0; i < 2; ++i) {
                LDM4(ah[i], st + 0 * TILE_B + aOffB + i * 1280 + kB);
                LDM4(al[i], st + 1 * TILE_B + aOffB + i * 1280 + kB);
            }
#pragma unroll
            for (int j = 0; j < 4; ++j) {
                uint32_t bh[4];
                LDM4(bh, st + 2 * TILE_B + bOffB + j * 1280 + kB);
                if (MODE == 1) {
                    uint32_t bl[4];
                    LDM4(bl, st + 3 * TILE_B + bOffB + j * 1280 + kB);
#pragma unroll
                    for (int i = 0; i < 2; ++i)
#pragma unroll
                        for (int h = 0; h < 2; ++h) {
                            const int jn = j * 2 + h;
                            MMA_BF16(acc[i][jn], ah[i], bh[h*2], bh[h*2+1]);
                            MMA_BF16(acc[i][jn], al[i], bh[h*2], bh[h*2+1]);
                            MMA_BF16(acc[i][jn], ah[i], bl[h*2], bl[h*2+1]);
                        }
                } else {
#pragma unroll
                    for (int i = 0; i < 2; ++i)
#pragma unroll
                        for (int h = 0; h < 2; ++h) {
                            const int jn = j * 2 + h;
                            MMA_BF16(acc[i][jn], ah[i], bh[h*2], bh[h*2+1]);
                            MMA_BF16(acc[i][jn], al[i], bh[h*2], bh[h*2+1]);
                        }
                }
            }
        }
        __syncthreads();
    }

    // ---- epilogue ----
    const int g  = lane >> 2, tg = lane & 3;
    const int b  = p0 >> 12;          // N tile lies within one batch image
    const int n0 = p0 & 4095;
#pragma unroll
    for (int i = 0; i < 2; ++i) {
#pragma unroll
        for (int r = 0; r < 2; ++r) {
            const int m = m0 + mb + i * 16 + r * 8 + g;
            if (MODE == 0) {
                __nv_bfloat16* crow = g_qkv + (size_t)m * PP + p0;
#pragma unroll
                for (int jn = 0; jn < 8; ++jn) {
                    const int col = nb + jn * 8 + tg * 2;
                    *reinterpret_cast<uint32_t*>(crow + col) =
                        pk2(acc[i][jn][r*2], acc[i][jn][r*2+1]);
                }
            } else {
                float* crow = g_div + (size_t)m * PP + p0;
                const float bb = bias[m];
                const float* vrow = vi + ((size_t)b * CC + m) * NN + n0;
                const float* irow = ir + ((size_t)b * CC + m) * NN + n0;
#pragma unroll
                for (int jn = 0; jn < 8; ++jn) {
                    const int col = nb + jn * 8 + tg * 2;
                    float2 v = make_float2(acc[i][jn][r*2], acc[i][jn][r*2+1]);
                    const float2 rv = *reinterpret_cast<const float2*>(vrow + col);
                    const float2 ri = *reinterpret_cast<const float2*>(irow + col);
                    v.x += bb + rv.x - ri.x;
                    v.y += bb + rv.y - ri.y;
                    *reinterpret_cast<float2*>(crow + col) = v;
                }
            }
        }
    }
}

// ---------------------------------------------------------------------------
// Kernel 3: dilated local attention. One thread per (b, head, pixel).
// Channels in 4 quarter-passes of 8; Q,K,V all bf16.
// grid (NN/256, 8 heads, BB), block 256.
// ---------------------------------------------------------------------------
__global__ __launch_bounds__(256)
void k_attn()
{
    const int b  = blockIdx.z;
    const int hg = blockIdx.y;               // global head 0..7
    const int n  = blockIdx.x * 256 + threadIdx.x;
    const int g  = hg >> 1;                  // dilation group
    const int dil = c_dil[g];
    const int qc = g * 64 + (hg & 1) * 32;   // channel base within 256

    const __nv_bfloat16* __restrict__ qp = g_qkv + (size_t)qc * PP + (size_t)b * NN;
    const __nv_bfloat16* __restrict__ kp = g_qkv + (size_t)(256 + qc) * PP + (size_t)b * NN;
    const __nv_bfloat16* __restrict__ vp = g_qkv + (size_t)(512 + qc) * PP + (size_t)b * NN;

    const int yy = n >> 6, xx = n & 63;

    // tap geometry (precompute validity + offset once)
    int   toff[9];
    bool  tok[9];
#pragma unroll
    for (int t = 0; t < 9; ++t) {
        const int py = yy + (t / 3 - 1) * dil;
        const int px = xx + (t % 3 - 1) * dil;
        tok[t]  = ((unsigned)py < 64u) && ((unsigned)px < 64u);
        toff[t] = py * 64 + px;
    }

    // ---- Pass A: logits over 4 channel quarters ----
    float logit[9] = {0.f, 0.f, 0.f, 0.f, 0.f, 0.f, 0.f, 0.f, 0.f};
#pragma unroll
    for (int qt = 0; qt < 4; ++qt) {
        const __nv_bfloat16* qph = qp + (size_t)(qt * 8) * PP;
        const __nv_bfloat16* kph = kp + (size_t)(qt * 8) * PP;
        float q[8];
#pragma unroll
        for (int c = 0; c < 8; ++c) q[c] = __bfloat162float(qph[(size_t)c * PP + n]);
#pragma unroll
        for (int t = 0; t < 9; ++t) {
            if (tok[t]) {
                const __nv_bfloat16* kcol = kph + toff[t];
                float s = 0.f;
#pragma unroll
                for (int c = 0; c < 8; ++c)
                    s += q[c] * __bfloat162float(kcol[(size_t)c * PP]);
                logit[t] += s;
            }
        }
    }

    float mx = -1e30f;
#pragma unroll
    for (int t = 0; t < 9; ++t) {
        logit[t] *= SCALE_F;       // zero-padded taps give exactly 0 (matches Unfold)
        mx = fmaxf(mx, logit[t]);
    }
    float den = 0.f;
#pragma unroll
    for (int t = 0; t < 9; ++t) { logit[t] = expf(logit[t] - mx); den += logit[t]; }
    const float inv = 1.0f / den;
#pragma unroll
    for (int t = 0; t < 9; ++t) logit[t] *= inv;

    // ---- Pass B: AV per quarter, write out immediately ----
    const size_t p = (size_t)b * NN + n;
#pragma unroll
    for (int qt = 0; qt < 4; ++qt) {
        const __nv_bfloat16* vph = vp + (size_t)(qt * 8) * PP;
        float acc[8] = {};
#pragma unroll
        for (int t = 0; t < 9; ++t) {
            if (tok[t]) {
                const float pw = logit[t];
                const __nv_bfloat16* vcol = vph + toff[t];
#pragma unroll
                for (int c = 0; c < 8; ++c)
                    acc[c] += pw * __bfloat162float(vcol[(size_t)c * PP]);
            }
        }
        uint32_t hx[4], lx[4];
#pragma unroll
        for (int e = 0; e < 4; ++e) {
            const float f0 = acc[e * 2];
            const float f1 = acc[e * 2 + 1];
            const float h0 = __bfloat162float(__float2bfloat16(f0));
            const float h1 = __bfloat162float(__float2bfloat16(f1));
            hx[e] = pk2(f0, f1);
            lx[e] = pk2(f0 - h0, f1 - h1);
        }
        *reinterpret_cast<uint4*>(g_yh + p * 256 + qc + qt * 8) =
            make_uint4(hx[0], hx[1], hx[2], hx[3]);
        *reinterpret_cast<uint4*>(g_yl + p * 256 + qc + qt * 8) =
            make_uint4(lx[0], lx[1], lx[2], lx[3]);
    }
}

// ---------------------------------------------------------------------------
// Kernel 5: per-(b,c) 64x64 @ 64x64 matmul: o = vi[b,c] @ div[b,c].
// g_div layout is [c][b*4096 + n].
// ---------------------------------------------------------------------------
__global__ __launch_bounds__(256)
void k_final(const float* __restrict__ vi, float* __restrict__ out, int dup)
{
    const int bc = blockIdx.x;
    const int b = bc >> 8, c = bc & 255;
    const float* __restrict__ Ap = vi    + (size_t)bc * 4096;
    const float* __restrict__ Bp = g_div + (size_t)c * PP + (size_t)b * NN;

    __shared__ __align__(16) float Asm[64][68];  // transposed
    __shared__ __align__(16) float Bsm[64][64];

    const int t  = threadIdx.x;
    const int tx = t & 15, ty = t >> 4;

#pragma unroll
    for (int it = 0; it < 4; ++it) {
        const int e  = t + 256 * it;
        const int r  = e >> 4;
        const int c4 = (e & 15) * 4;
        const float4 a4 = *reinterpret_cast<const float4*>(Ap + r * 64 + c4);
        Asm[c4 + 0][r] = a4.x; Asm[c4 + 1][r] = a4.y;
        Asm[c4 + 2][r] = a4.z; Asm[c4 + 3][r] = a4.w;
        *reinterpret_cast<float4*>(&Bsm[r][c4]) =
            *reinterpret_cast<const float4*>(Bp + r * 64 + c4);
    }
    __syncthreads();

    float acc[4][4] = {};
#pragma unroll
    for (int k = 0; k < 64; ++k) {
        float a_[4], b_[4];
#pragma unroll
        for (int i = 0; i < 4; ++i) a_[i] = Asm[k][ty * 4 + i];
#pragma unroll
        for (int j = 0; j < 4; ++j) b_[j] = Bsm[k][tx * 4 + j];
#pragma unroll
        for (int i = 0; i < 4; ++i)
#pragma unroll
            for (int j = 0; j < 4; ++j)
                acc[i][j] += a_[i] * b_[j];
    }

#pragma unroll
    for (int i = 0; i < 4; ++i) {
        const size_t idx = (size_t)bc * 4096 + (size_t)(ty * 4 + i) * 64 + tx * 4;
        const float4 v = make_float4(acc[i][0], acc[i][1], acc[i][2], acc[i][3]);
        *reinterpret_cast<float4*>(out + idx) = v;
        if (dup) *reinterpret_cast<float4*>(out + (size_t)NUMEL + idx) = v;
    }
}

// ---------------------------------------------------------------------------
extern "C" void kernel_launch(void* const* d_in, const int* in_sizes, int n_in,
                              void* d_out, int out_size)
{
    const float* vi     = (const float*)d_in[0];
    const float* ir     = (const float*)d_in[1];
    const float* w_qkv  = (const float*)d_in[2];
    const float* proj_w = (const float*)d_in[3];
    const float* proj_b = (const float*)d_in[4];
    const float* ln_g   = (const float*)d_in[5];
    const float* ln_b   = (const float*)d_in[6];
    float* out = (float*)d_out;

    const int dup = (out_size >= 2 * NUMEL) ? 1 : 0;
    const int SMEM_G0 = 2 * 3 * TILE_B;   // 61440 B (2-term, 3 tiles)
    const int SMEM_G1 = 2 * 4 * TILE_B;   // 81920 B (3-term, 4 tiles)

    static bool attr_done = false;
    if (!attr_done) {
        cudaFuncSetAttribute(k_gemm_mma<0>, cudaFuncAttributeMaxDynamicSharedMemorySize, SMEM_G0);
        cudaFuncSetAttribute(k_gemm_mma<1>, cudaFuncAttributeMaxDynamicSharedMemorySize, SMEM_G1);
        attr_done = true;
    }

    // 0. weight bf16 split
    k_wsplit<<<1024, 256>>>(w_qkv, proj_w);
    // 1. sub + LN -> Xt hi (transposed bf16)
    k_subln<<<dim3(NN / 32, BB), dim3(32, 8)>>>(vi, ir, ln_g, ln_b);
    // 2. QKV GEMM (HMMA, 2-term): g_qkv all-bf16
    k_gemm_mma<0><<<dim3(PP / 128, 6), 256, SMEM_G0>>>(nullptr, nullptr, nullptr);
    // 3. dilated local attention -> Yt hi/lo
    k_attn<<<dim3(NN / 256, 8, BB), 256>>>();
    // 4. proj GEMM (HMMA, 3-term) + bias + residual -> g_div
    k_gemm_mma<1><<<dim3(PP / 128, 2), 256, SMEM_G1>>>(proj_b, vi, ir);
    // 5. batched 64x64 matmul: out = vi @ div, duplicated
    k_final<<<BB * CC, 256>>>(vi, out, dup);
}